// round 11
// baseline (speedup 1.0000x reference)
#include <cuda_runtime.h>
#include <math.h>

// ---------------------------------------------------------------------------
// Multi-scale region distillation loss — SINGLE fused kernel.
//
// pass1 streaming geometry (unchanged, measured-good): block = (<=2048 px) x
// (64 ch), 8 px/thread register accumulators; warp reads 1KB contiguous per
// tensor per channel step. NCG=4 channel groups store partial dot/na/nb.
//
// R11: the reduction "pass2" (a fixed, unexplained ~50us as a separate
// launch) is fused in as a per-chunk epilogue: the LAST channel-group block
// of each pixel chunk (per-chunk atomic counter) re-reads the 12 partial
// slots (L2-hot), computes cosine + class bins. A global chunk counter
// triggers the final loss + scratch reset in the last finisher block.
// ---------------------------------------------------------------------------

#define NUM_SCALES 4
#define MAXC 32
#define LAB_DIM 512
#define THREADS 256
#define NCG 4                    // channel groups per scale
#define MAXPIX 348160
#define MAXCHUNKS 256

__device__ float        g_part[NCG * 3 * MAXPIX];   // partial dot/na/nb slots
__device__ double       g_seg[NUM_SCALES * MAXC];
__device__ float        g_cnt[NUM_SCALES * MAXC];
__device__ unsigned int g_chunk_done[MAXCHUNKS];    // zero-init at load
__device__ unsigned int g_final_done = 0;           // zero-init at load

struct ScaleDesc {
    const float* f;
    const float* fo;
    int C;           // channels
    int Cg;          // channels per group (C / NCG)
    int W;           // spatial width (=H)
    int HW;          // H*W
    int pixels;      // B*HW
    int PXB;         // pixels per block chunk = min(HW, 2048)
    int npx;         // pixels per thread = PXB / 256
    int block_base;  // first block of this scale
    int chunk_base;  // first chunk id of this scale
    int pix_off;     // global pixel offset of this scale
    int sub;         // LAB_DIM / H
};
struct AllDesc { ScaleDesc s[NUM_SCALES]; };

// ---- streaming inner loop: NPX pixels/thread, UNR channels per batch ------
template<int NPX, int UNR>
__device__ __forceinline__ void accum_loop(
    const float* __restrict__ fA, const float* __restrict__ fO,
    int HW, int Cg, float* dot, float* na, float* nb)
{
    #pragma unroll 1
    for (int c = 0; c < Cg; c += UNR) {
        float a[NPX * UNR], o[NPX * UNR];
        #pragma unroll
        for (int u = 0; u < UNR; ++u)
            #pragma unroll
            for (int k = 0; k < NPX; ++k)
                a[u * NPX + k] = fA[(size_t)(c + u) * HW + (k << 8)];
        #pragma unroll
        for (int u = 0; u < UNR; ++u)
            #pragma unroll
            for (int k = 0; k < NPX; ++k)
                o[u * NPX + k] = fO[(size_t)(c + u) * HW + (k << 8)];
        #pragma unroll
        for (int u = 0; u < UNR; ++u)
            #pragma unroll
            for (int k = 0; k < NPX; ++k) {
                const float av = a[u * NPX + k], ov = o[u * NPX + k];
                dot[k] = fmaf(av, ov, dot[k]);
                na[k]  = fmaf(av, av, na[k]);
                nb[k]  = fmaf(ov, ov, nb[k]);
            }
    }
}

__global__ void __launch_bounds__(THREADS, 4)
msrd_fused(AllDesc d, int NPIX, int NCHUNKS, const int* __restrict__ lab,
           const int* __restrict__ ncls_p, const int* __restrict__ nold_p,
           float* __restrict__ out)
{
    __shared__ float s_seg[MAXC];
    __shared__ float s_cnt[MAXC];
    __shared__ int   s_chunk_last;
    __shared__ int   s_final_last;
    if (threadIdx.x < MAXC) { s_seg[threadIdx.x] = 0.f; s_cnt[threadIdx.x] = 0.f; }

    int sidx;
    if      ((int)blockIdx.x < d.s[1].block_base) sidx = 0;
    else if ((int)blockIdx.x < d.s[2].block_base) sidx = 1;
    else if ((int)blockIdx.x < d.s[3].block_base) sidx = 2;
    else                                          sidx = 3;
    const ScaleDesc sd = d.s[sidx];

    const int local = (int)blockIdx.x - sd.block_base;
    const int pxb   = local >> 2;            // pixel-chunk index within scale
    const int cg    = local & (NCG - 1);     // channel group
    const int t     = (int)threadIdx.x;

    const int px0 = pxb * sd.PXB;            // chunk start pixel within scale
    const int b   = px0 / sd.HW;             // PXB divides HW -> single image
    const int p0  = px0 - b * sd.HW;

    // -------------------- streaming phase --------------------
    {
        const float* __restrict__ fA =
            sd.f  + ((size_t)b * sd.C + (size_t)cg * sd.Cg) * sd.HW + p0 + t;
        const float* __restrict__ fO =
            sd.fo + ((size_t)b * sd.C + (size_t)cg * sd.Cg) * sd.HW + p0 + t;

        float dot[8] = {0,0,0,0,0,0,0,0};
        float na [8] = {0,0,0,0,0,0,0,0};
        float nb [8] = {0,0,0,0,0,0,0,0};

        if      (sd.npx == 8) accum_loop<8,1>(fA, fO, sd.HW, sd.Cg, dot, na, nb);
        else if (sd.npx == 4) accum_loop<4,2>(fA, fO, sd.HW, sd.Cg, dot, na, nb);
        else                  accum_loop<1,4>(fA, fO, sd.HW, sd.Cg, dot, na, nb);

        const int gpix0 = sd.pix_off + px0 + t;
        float* __restrict__ pd = g_part + (size_t)(cg * 3 + 0) * NPIX;
        float* __restrict__ pa = g_part + (size_t)(cg * 3 + 1) * NPIX;
        float* __restrict__ pb = g_part + (size_t)(cg * 3 + 2) * NPIX;
        #pragma unroll
        for (int k = 0; k < 8; ++k) {
            if (k < sd.npx) {
                pd[gpix0 + (k << 8)] = dot[k];
                pa[gpix0 + (k << 8)] = na[k];
                pb[gpix0 + (k << 8)] = nb[k];
            }
        }
    }

    // -------------------- chunk completion --------------------
    __threadfence();    // make this thread's partial stores globally visible
    __syncthreads();    // all threads' stores done (each already fenced)
    if (t == 0) {
        const unsigned int n = atomicAdd(&g_chunk_done[sd.chunk_base + pxb], 1u);
        s_chunk_last = (n == NCG - 1) ? 1 : 0;
    }
    __syncthreads();
    if (!s_chunk_last) return;

    // -------------------- per-chunk reduction (last CG block) --------------
    {
        #pragma unroll 1
        for (int k = 0; k < 8; ++k) {
            if (k >= sd.npx) break;
            const int i = sd.pix_off + px0 + t + (k << 8);   // global pixel id
            float dot = 0.f, na = 0.f, nb = 0.f;
            #pragma unroll
            for (int g = 0; g < NCG; ++g) {
                dot += g_part[(size_t)(g * 3 + 0) * NPIX + i];
                na  += g_part[(size_t)(g * 3 + 1) * NPIX + i];
                nb  += g_part[(size_t)(g * 3 + 2) * NPIX + i];
            }
            const float nf  = fmaxf(sqrtf(na), 1e-8f);
            const float nfo = fmaxf(sqrtf(nb), 1e-8f);
            const float sim = dot / (nf * nfo);

            const int p = p0 + t + (k << 8);
            const int h = p / sd.W;
            const int w = p - h * sd.W;
            const int l = lab[(size_t)b * LAB_DIM * LAB_DIM
                              + (size_t)(h * sd.sub) * LAB_DIM + (size_t)w * sd.sub];
            if (l >= 0 && l < MAXC) {
                atomicAdd(&s_seg[l], sim);
                atomicAdd(&s_cnt[l], 1.0f);
            }
        }
    }

    __syncthreads();
    if (t < MAXC) {
        const float cs = s_cnt[t];
        if (cs != 0.0f) {
            atomicAdd(&g_seg[sidx * MAXC + t], (double)s_seg[t]);
            atomicAdd(&g_cnt[sidx * MAXC + t], cs);
        }
    }

    // -------------------- global finalize (last chunk finisher) ------------
    __syncthreads();
    if (t == 0) {
        __threadfence();
        const unsigned int n = atomicAdd(&g_final_done, 1u);
        s_final_last = (n == (unsigned)NCHUNKS - 1) ? 1 : 0;
    }
    __syncthreads();
    if (!s_final_last) return;

    __threadfence();    // all finishers' g_seg/g_cnt atomics visible
    if (t == 0) {
        const int nc = ncls_p ? *ncls_p : 21;
        const int no = nold_p ? *nold_p : 15;
        const double wts[NUM_SCALES] = {1.0, 2.0, 3.0, 4.0};
        double loss = 0.0;
        for (int s = 0; s < NUM_SCALES; ++s) {
            for (int cls = 0; cls < nc && cls < MAXC; ++cls) {
                const float cnt = g_cnt[s * MAXC + cls];
                if (cnt > 0.0f) {
                    const double mean = g_seg[s * MAXC + cls] / (double)cnt;
                    double factor;
                    if (cls == 0)        factor = (double)no / (double)nc;
                    else if (cls <= no)  factor = 1.0;
                    else                 factor = 0.0;
                    loss += wts[s] * factor * (1.0 - mean);
                }
            }
        }
        *out = (float)loss;
    }

    __syncthreads();    // loss read complete before resets
    if (t == 0) g_final_done = 0;
    if (t < NCHUNKS) g_chunk_done[t] = 0;
    if (t < NUM_SCALES * MAXC / 2) {
        const int r = t * 2;
        g_seg[r] = 0.0;  g_seg[r + 1] = 0.0;
        g_cnt[r] = 0.0f; g_cnt[r + 1] = 0.0f;
    }
    // g_part needs no reset — fully overwritten every replay.
}

extern "C" void kernel_launch(void* const* d_in, const int* in_sizes, int n_in,
                              void* d_out, int out_size)
{
    const int* lab = (const int*)d_in[0];
    const int B = in_sizes[0] / (LAB_DIM * LAB_DIM);

    // ---- identify feature buffers by size (order-agnostic) ----
    const float* fbuf[NUM_SCALES]  = {nullptr, nullptr, nullptr, nullptr};
    const float* fobuf[NUM_SCALES] = {nullptr, nullptr, nullptr, nullptr};
    long         szs[NUM_SCALES]   = {0, 0, 0, 0};
    int ns = 0;
    const int* scalar_ptrs[2] = {nullptr, nullptr};
    int nscalar = 0;

    for (int i = 1; i < n_in; ++i) {
        const long sz = in_sizes[i];
        if (sz <= 1) {
            if (nscalar < 2) scalar_ptrs[nscalar++] = (const int*)d_in[i];
            continue;
        }
        int j = 0;
        while (j < ns && szs[j] != sz) ++j;
        if (j == ns && ns < NUM_SCALES) {
            szs[ns] = sz; fbuf[ns] = (const float*)d_in[i]; ++ns;
        } else if (j < ns) {
            fobuf[j] = (const float*)d_in[i];
        }
    }
    for (int i = 0; i < ns; ++i)
        for (int j = i + 1; j < ns; ++j)
            if (szs[j] > szs[i]) {
                long ts = szs[i]; szs[i] = szs[j]; szs[j] = ts;
                const float* tf = fbuf[i]; fbuf[i] = fbuf[j]; fbuf[j] = tf;
                const float* to = fobuf[i]; fobuf[i] = fobuf[j]; fobuf[j] = to;
            }

    // ---- per-scale descriptors ----
    AllDesc ad;
    int block_base = 0;
    int chunk_base = 0;
    int pix_off = 0;
    for (int s = 0; s < NUM_SCALES; ++s) {
        const int HW_dim = 128 >> s;             // 128,64,32,16
        const int HW     = HW_dim * HW_dim;
        const int C      = (int)(szs[s] / ((long)B * HW));
        const int pixels = B * HW;
        const int PXB    = (HW < 2048) ? HW : 2048;
        const int npx    = PXB / THREADS;
        const int nchk   = pixels / PXB;

        ad.s[s].f          = fbuf[s];
        ad.s[s].fo         = fobuf[s];
        ad.s[s].C          = C;
        ad.s[s].Cg         = C / NCG;
        ad.s[s].W          = HW_dim;
        ad.s[s].HW         = HW;
        ad.s[s].pixels     = pixels;
        ad.s[s].PXB        = PXB;
        ad.s[s].npx        = npx;
        ad.s[s].block_base = block_base;
        ad.s[s].chunk_base = chunk_base;
        ad.s[s].pix_off    = pix_off;
        ad.s[s].sub        = LAB_DIM / HW_dim;
        block_base += nchk * NCG;
        chunk_base += nchk;
        pix_off    += pixels;
    }
    const int NPIX    = pix_off;
    const int NCHUNKS = chunk_base;

    msrd_fused<<<block_base, THREADS>>>(ad, NPIX, NCHUNKS, lab,
                                        scalar_ptrs[0], scalar_ptrs[1],
                                        (float*)d_out);
}

// round 12
// speedup vs baseline: 1.1923x; 1.1923x over previous
#include <cuda_runtime.h>
#include <math.h>
#include <stdint.h>

// ---------------------------------------------------------------------------
// Multi-scale region distillation loss — single kernel, cp.async pipeline.
//
// R12: every synchronous-LDG geometry (R5-R11) hit a ~3.3TB/s wall with DRAM
// 60% idle (latency-bound; scoreboard-coupled LDG can't keep the queue full).
// Switch to cp.async.cg (LDGSTS) 8-stage smem pipeline: in-flight bytes are
// set by pipeline depth (7 stages x 2KB x ~4.6 blocks/SM = 64KB/SM), not by
// warp count or register allocation.
//
// Geometry: block = 256 px x 256 ch (uniform; 680 equal blocks).
// Stage = one channel row (f 1KB + fo 1KB, contiguous). Threads 0..63 copy f,
// 64..127 copy fo (16B each); all 256 threads compute 1 px each from smem.
// ---------------------------------------------------------------------------

#define NUM_SCALES 4
#define MAXC 32
#define LAB_DIM 512
#define THREADS 256
#define PXB 256                 // pixels per block/chunk
#define STAGES 8
#define SLOT_FLOATS 512         // f[0..255] + fo[256..511] per stage

__device__ double       g_seg[NUM_SCALES * MAXC];   // zero-init at load
__device__ float        g_cnt[NUM_SCALES * MAXC];   // zero-init at load
__device__ unsigned int g_blocks_done = 0;          // zero-init at load

struct ScaleDesc {
    const float* f;
    const float* fo;
    int C;           // channels
    int W;           // spatial width (=H)
    int HW;          // H*W
    int block_base;  // first block of this scale
    int sub;         // LAB_DIM / H
};
struct AllDesc { ScaleDesc s[NUM_SCALES]; };

__device__ __forceinline__ void cp16(uint32_t dst, const void* src) {
    asm volatile("cp.async.cg.shared.global [%0], [%1], 16;"
                 :: "r"(dst), "l"(src) : "memory");
}
__device__ __forceinline__ void cp_commit() {
    asm volatile("cp.async.commit_group;" ::: "memory");
}
__device__ __forceinline__ void cp_wait6() {
    asm volatile("cp.async.wait_group 6;" ::: "memory");
}

__global__ void __launch_bounds__(THREADS, 6)
msrd_kernel(AllDesc d, const int* __restrict__ lab,
            const int* __restrict__ ncls_p, const int* __restrict__ nold_p,
            float* __restrict__ out)
{
    __shared__ float s_tile[STAGES][SLOT_FLOATS];
    __shared__ float s_seg[MAXC];
    __shared__ float s_cnt[MAXC];
    __shared__ int   s_is_last;

    const int t = (int)threadIdx.x;
    if (t < MAXC) { s_seg[t] = 0.f; s_cnt[t] = 0.f; }

    int sidx;
    if      ((int)blockIdx.x < d.s[1].block_base) sidx = 0;
    else if ((int)blockIdx.x < d.s[2].block_base) sidx = 1;
    else if ((int)blockIdx.x < d.s[3].block_base) sidx = 2;
    else                                          sidx = 3;
    const ScaleDesc sd = d.s[sidx];

    const int chunk = (int)blockIdx.x - sd.block_base;
    const int px0   = chunk * PXB;               // pixel offset within scale
    const int b     = px0 / sd.HW;               // PXB divides HW
    const int p0    = px0 - b * sd.HW;
    const int HW    = sd.HW;
    const int C     = sd.C;

    // per-thread cp.async source / dest (threads 0..63: f, 64..127: fo)
    const bool issuer = (t < 128);
    const float* __restrict__ fA =
        sd.f  + (size_t)b * C * HW + p0;
    const float* __restrict__ fO =
        sd.fo + (size_t)b * C * HW + p0;
    const float* src0 = (t < 64) ? (fA + t * 4) : (fO + (t - 64) * 4);
    const uint32_t tile_u32 =
        (uint32_t)__cvta_generic_to_shared(&s_tile[0][0]);
    const uint32_t dst_off =
        (t < 64) ? (uint32_t)(t * 16) : (uint32_t)(1024 + (t - 64) * 16);

    // ---------------- pipeline prologue: stages 0..6 ----------------
    #pragma unroll
    for (int c = 0; c < STAGES - 1; ++c) {
        if (issuer) cp16(tile_u32 + (uint32_t)(c & (STAGES - 1)) * 2048 + dst_off,
                         src0 + (size_t)c * HW);
        cp_commit();
    }

    // ---------------- main loop over channels ----------------
    float dot = 0.f, na = 0.f, nb = 0.f;
    #pragma unroll 1
    for (int c = 0; c < C; ++c) {
        cp_wait6();          // oldest outstanding stage (c) has landed
        __syncthreads();     // visible to all threads

        const int sl = c & (STAGES - 1);
        const float a = s_tile[sl][t];
        const float o = s_tile[sl][256 + t];
        dot = fmaf(a, o, dot);
        na  = fmaf(a, a, na);
        nb  = fmaf(o, o, nb);

        // refill slot (c+7)&7 == (c-1)&7, consumed by everyone before the
        // sync above; safe to overwrite.
        const int cn = c + STAGES - 1;
        if (issuer && cn < C)
            cp16(tile_u32 + (uint32_t)(cn & (STAGES - 1)) * 2048 + dst_off,
                 src0 + (size_t)cn * HW);
        cp_commit();
    }

    // ---------------- per-pixel epilogue ----------------
    {
        const float nf  = fmaxf(sqrtf(na), 1e-8f);
        const float nfo = fmaxf(sqrtf(nb), 1e-8f);
        const float sim = dot / (nf * nfo);

        const int p = p0 + t;
        const int h = p / sd.W;
        const int w = p - h * sd.W;
        const int l = lab[(size_t)b * LAB_DIM * LAB_DIM
                          + (size_t)(h * sd.sub) * LAB_DIM + (size_t)w * sd.sub];
        if (l >= 0 && l < MAXC) {
            atomicAdd(&s_seg[l], sim);
            atomicAdd(&s_cnt[l], 1.0f);
        }
    }

    __syncthreads();
    if (t < MAXC) {
        const float cs = s_cnt[t];
        if (cs != 0.0f) {
            atomicAdd(&g_seg[sidx * MAXC + t], (double)s_seg[t]);
            atomicAdd(&g_cnt[sidx * MAXC + t], cs);
        }
    }

    // ---------------- last-block finalize ----------------
    __syncthreads();
    if (t == 0) {
        __threadfence();
        const unsigned int done = atomicAdd(&g_blocks_done, 1u);
        s_is_last = (done == gridDim.x - 1) ? 1 : 0;
    }
    __syncthreads();
    if (!s_is_last) return;

    __threadfence();
    if (t == 0) {
        const int nc = ncls_p ? *ncls_p : 21;
        const int no = nold_p ? *nold_p : 15;
        const double wts[NUM_SCALES] = {1.0, 2.0, 3.0, 4.0};
        double loss = 0.0;
        for (int s = 0; s < NUM_SCALES; ++s) {
            for (int cls = 0; cls < nc && cls < MAXC; ++cls) {
                const float cnt = g_cnt[s * MAXC + cls];
                if (cnt > 0.0f) {
                    const double mean = g_seg[s * MAXC + cls] / (double)cnt;
                    double factor;
                    if (cls == 0)        factor = (double)no / (double)nc;
                    else if (cls <= no)  factor = 1.0;
                    else                 factor = 0.0;
                    loss += wts[s] * factor * (1.0 - mean);
                }
            }
        }
        *out = (float)loss;
    }

    __syncthreads();   // loss read complete before resets
    if (t == 0) g_blocks_done = 0;
    if (t < NUM_SCALES * MAXC / 2) {
        const int r = t * 2;
        g_seg[r] = 0.0;  g_seg[r + 1] = 0.0;
        g_cnt[r] = 0.0f; g_cnt[r + 1] = 0.0f;
    }
}

extern "C" void kernel_launch(void* const* d_in, const int* in_sizes, int n_in,
                              void* d_out, int out_size)
{
    const int* lab = (const int*)d_in[0];
    const int B = in_sizes[0] / (LAB_DIM * LAB_DIM);

    // ---- identify feature buffers by size (order-agnostic) ----
    const float* fbuf[NUM_SCALES]  = {nullptr, nullptr, nullptr, nullptr};
    const float* fobuf[NUM_SCALES] = {nullptr, nullptr, nullptr, nullptr};
    long         szs[NUM_SCALES]   = {0, 0, 0, 0};
    int ns = 0;
    const int* scalar_ptrs[2] = {nullptr, nullptr};
    int nscalar = 0;

    for (int i = 1; i < n_in; ++i) {
        const long sz = in_sizes[i];
        if (sz <= 1) {
            if (nscalar < 2) scalar_ptrs[nscalar++] = (const int*)d_in[i];
            continue;
        }
        int j = 0;
        while (j < ns && szs[j] != sz) ++j;
        if (j == ns && ns < NUM_SCALES) {
            szs[ns] = sz; fbuf[ns] = (const float*)d_in[i]; ++ns;
        } else if (j < ns) {
            fobuf[j] = (const float*)d_in[i];
        }
    }
    for (int i = 0; i < ns; ++i)
        for (int j = i + 1; j < ns; ++j)
            if (szs[j] > szs[i]) {
                long ts = szs[i]; szs[i] = szs[j]; szs[j] = ts;
                const float* tf = fbuf[i]; fbuf[i] = fbuf[j]; fbuf[j] = tf;
                const float* to = fobuf[i]; fobuf[i] = fobuf[j]; fobuf[j] = to;
            }

    // ---- per-scale descriptors (uniform 256-px chunks) ----
    AllDesc ad;
    int block_base = 0;
    for (int s = 0; s < NUM_SCALES; ++s) {
        const int HW_dim = 128 >> s;             // 128,64,32,16
        const int HW     = HW_dim * HW_dim;
        const int C      = (int)(szs[s] / ((long)B * HW));
        const int pixels = B * HW;
        const int nblk   = pixels / PXB;

        ad.s[s].f          = fbuf[s];
        ad.s[s].fo         = fobuf[s];
        ad.s[s].C          = C;
        ad.s[s].W          = HW_dim;
        ad.s[s].HW         = HW;
        ad.s[s].block_base = block_base;
        ad.s[s].sub        = LAB_DIM / HW_dim;
        block_base += nblk;
    }

    msrd_kernel<<<block_base, THREADS>>>(ad, lab,
                                         scalar_ptrs[0], scalar_ptrs[1],
                                         (float*)d_out);
}

// round 13
// speedup vs baseline: 1.2461x; 1.0451x over previous
#include <cuda_runtime.h>
#include <math.h>
#include <stdint.h>

// ---------------------------------------------------------------------------
// Multi-scale region distillation loss — single kernel, cp.async pipeline.
//
// R13: R12's cp.async pipeline broke the LDG latency wall (98.5us, DRAM 48%)
// but became front-end bound (issue 58.8%) — one barrier + wait per CHANNEL.
// Widen stage to 4 channels (8KB): 4x fewer barriers/waits, 26 instr per
// 32B/thread (was ~40), and more in-flight bytes (3 stages x 8KB x ~4.6
// blocks/SM ~= 110KB/SM).
//
// Geometry: block = 256 px x 256 ch (680 uniform blocks). Stage = 4 channel
// rows of f (4KB) + fo (4KB). All 256 threads issue 2x cp16 per stage.
// ---------------------------------------------------------------------------

#define NUM_SCALES 4
#define MAXC 32
#define LAB_DIM 512
#define THREADS 256
#define PXB 256                 // pixels per block/chunk
#define STAGES 4
#define CPS 4                   // channels per stage
#define STAGE_FLOATS (CPS * PXB * 2)   // 2048 floats = 8KB

__device__ double       g_seg[NUM_SCALES * MAXC];   // zero-init at load
__device__ float        g_cnt[NUM_SCALES * MAXC];   // zero-init at load
__device__ unsigned int g_blocks_done = 0;          // zero-init at load

struct ScaleDesc {
    const float* f;
    const float* fo;
    int C;           // channels
    int W;           // spatial width (=H)
    int HW;          // H*W
    int block_base;  // first block of this scale
    int sub;         // LAB_DIM / H
};
struct AllDesc { ScaleDesc s[NUM_SCALES]; };

__device__ __forceinline__ void cp16(uint32_t dst, const void* src) {
    asm volatile("cp.async.cg.shared.global [%0], [%1], 16;"
                 :: "r"(dst), "l"(src) : "memory");
}
__device__ __forceinline__ void cp_commit() {
    asm volatile("cp.async.commit_group;" ::: "memory");
}
__device__ __forceinline__ void cp_wait2() {
    asm volatile("cp.async.wait_group 2;" ::: "memory");
}

__global__ void __launch_bounds__(THREADS, 5)
msrd_kernel(AllDesc d, const int* __restrict__ lab,
            const int* __restrict__ ncls_p, const int* __restrict__ nold_p,
            float* __restrict__ out)
{
    __shared__ float s_tile[STAGES][STAGE_FLOATS];   // 32KB
    __shared__ float s_seg[MAXC];
    __shared__ float s_cnt[MAXC];
    __shared__ int   s_is_last;

    const int t = (int)threadIdx.x;
    if (t < MAXC) { s_seg[t] = 0.f; s_cnt[t] = 0.f; }

    int sidx;
    if      ((int)blockIdx.x < d.s[1].block_base) sidx = 0;
    else if ((int)blockIdx.x < d.s[2].block_base) sidx = 1;
    else if ((int)blockIdx.x < d.s[3].block_base) sidx = 2;
    else                                          sidx = 3;
    const ScaleDesc sd = d.s[sidx];

    const int chunk = (int)blockIdx.x - sd.block_base;
    const int px0   = chunk * PXB;               // pixel offset within scale
    const int b     = px0 / sd.HW;               // PXB divides HW
    const int p0    = px0 - b * sd.HW;
    const int HW    = sd.HW;
    const int C     = sd.C;
    const int ngrp  = C / CPS;                   // channel groups (64)

    // Each thread copies 16B of f and 16B of fo per stage.
    // Within a 4-channel stage: thread t covers channel (t>>6), bytes
    // (t&63)*16 of that 1KB channel row.
    const float* __restrict__ fA = sd.f  + (size_t)b * C * HW + p0;
    const float* __restrict__ fO = sd.fo + (size_t)b * C * HW + p0;
    const float* srcA0 = fA + (size_t)(t >> 6) * HW + (t & 63) * 4;
    const float* srcO0 = fO + (size_t)(t >> 6) * HW + (t & 63) * 4;
    const size_t grp_stride = (size_t)CPS * HW;  // floats per channel group

    const uint32_t tile_u32 =
        (uint32_t)__cvta_generic_to_shared(&s_tile[0][0]);
    const uint32_t dstA = (uint32_t)(t * 16);          // f region [0,4096)
    const uint32_t dstO = (uint32_t)(4096 + t * 16);   // fo region [4096,8192)

    // ---------------- pipeline prologue: groups 0..2 ----------------
    #pragma unroll
    for (int g = 0; g < STAGES - 1; ++g) {
        const uint32_t sb = tile_u32 + (uint32_t)g * (STAGE_FLOATS * 4);
        cp16(sb + dstA, srcA0 + (size_t)g * grp_stride);
        cp16(sb + dstO, srcO0 + (size_t)g * grp_stride);
        cp_commit();
    }

    // ---------------- main loop over channel groups ----------------
    float dot = 0.f, na = 0.f, nb = 0.f;
    #pragma unroll 1
    for (int g = 0; g < ngrp; ++g) {
        cp_wait2();          // group g landed (<=2 groups outstanding)
        __syncthreads();

        const int sl = g & (STAGES - 1);
        const float* __restrict__ fa = &s_tile[sl][0];
        const float* __restrict__ fo2 = &s_tile[sl][CPS * PXB];
        #pragma unroll
        for (int c = 0; c < CPS; ++c) {
            const float a = fa [c * PXB + t];
            const float o = fo2[c * PXB + t];
            dot = fmaf(a, o, dot);
            na  = fmaf(a, a, na);
            nb  = fmaf(o, o, nb);
        }

        // refill slot (g+3)&3 == (g-1)&3: consumed by all threads in the
        // previous iteration, before this iteration's barrier. Safe.
        const int gn = g + STAGES - 1;
        if (gn < ngrp) {
            const uint32_t sb = tile_u32 + (uint32_t)(gn & (STAGES - 1))
                                           * (STAGE_FLOATS * 4);
            cp16(sb + dstA, srcA0 + (size_t)gn * grp_stride);
            cp16(sb + dstO, srcO0 + (size_t)gn * grp_stride);
        }
        cp_commit();
    }

    // ---------------- per-pixel epilogue ----------------
    {
        const float nf  = fmaxf(sqrtf(na), 1e-8f);
        const float nfo = fmaxf(sqrtf(nb), 1e-8f);
        const float sim = dot / (nf * nfo);

        const int p = p0 + t;
        const int h = p / sd.W;
        const int w = p - h * sd.W;
        const int l = lab[(size_t)b * LAB_DIM * LAB_DIM
                          + (size_t)(h * sd.sub) * LAB_DIM + (size_t)w * sd.sub];
        if (l >= 0 && l < MAXC) {
            atomicAdd(&s_seg[l], sim);
            atomicAdd(&s_cnt[l], 1.0f);
        }
    }

    __syncthreads();
    if (t < MAXC) {
        const float cs = s_cnt[t];
        if (cs != 0.0f) {
            atomicAdd(&g_seg[sidx * MAXC + t], (double)s_seg[t]);
            atomicAdd(&g_cnt[sidx * MAXC + t], cs);
        }
    }

    // ---------------- last-block finalize ----------------
    __syncthreads();
    if (t == 0) {
        __threadfence();
        const unsigned int done = atomicAdd(&g_blocks_done, 1u);
        s_is_last = (done == gridDim.x - 1) ? 1 : 0;
    }
    __syncthreads();
    if (!s_is_last) return;

    __threadfence();
    if (t == 0) {
        const int nc = ncls_p ? *ncls_p : 21;
        const int no = nold_p ? *nold_p : 15;
        const double wts[NUM_SCALES] = {1.0, 2.0, 3.0, 4.0};
        double loss = 0.0;
        for (int s = 0; s < NUM_SCALES; ++s) {
            for (int cls = 0; cls < nc && cls < MAXC; ++cls) {
                const float cnt = g_cnt[s * MAXC + cls];
                if (cnt > 0.0f) {
                    const double mean = g_seg[s * MAXC + cls] / (double)cnt;
                    double factor;
                    if (cls == 0)        factor = (double)no / (double)nc;
                    else if (cls <= no)  factor = 1.0;
                    else                 factor = 0.0;
                    loss += wts[s] * factor * (1.0 - mean);
                }
            }
        }
        *out = (float)loss;
    }

    __syncthreads();   // loss read complete before resets
    if (t == 0) g_blocks_done = 0;
    if (t < NUM_SCALES * MAXC / 2) {
        const int r = t * 2;
        g_seg[r] = 0.0;  g_seg[r + 1] = 0.0;
        g_cnt[r] = 0.0f; g_cnt[r + 1] = 0.0f;
    }
}

extern "C" void kernel_launch(void* const* d_in, const int* in_sizes, int n_in,
                              void* d_out, int out_size)
{
    const int* lab = (const int*)d_in[0];
    const int B = in_sizes[0] / (LAB_DIM * LAB_DIM);

    // ---- identify feature buffers by size (order-agnostic) ----
    const float* fbuf[NUM_SCALES]  = {nullptr, nullptr, nullptr, nullptr};
    const float* fobuf[NUM_SCALES] = {nullptr, nullptr, nullptr, nullptr};
    long         szs[NUM_SCALES]   = {0, 0, 0, 0};
    int ns = 0;
    const int* scalar_ptrs[2] = {nullptr, nullptr};
    int nscalar = 0;

    for (int i = 1; i < n_in; ++i) {
        const long sz = in_sizes[i];
        if (sz <= 1) {
            if (nscalar < 2) scalar_ptrs[nscalar++] = (const int*)d_in[i];
            continue;
        }
        int j = 0;
        while (j < ns && szs[j] != sz) ++j;
        if (j == ns && ns < NUM_SCALES) {
            szs[ns] = sz; fbuf[ns] = (const float*)d_in[i]; ++ns;
        } else if (j < ns) {
            fobuf[j] = (const float*)d_in[i];
        }
    }
    for (int i = 0; i < ns; ++i)
        for (int j = i + 1; j < ns; ++j)
            if (szs[j] > szs[i]) {
                long ts = szs[i]; szs[i] = szs[j]; szs[j] = ts;
                const float* tf = fbuf[i]; fbuf[i] = fbuf[j]; fbuf[j] = tf;
                const float* to = fobuf[i]; fobuf[i] = fobuf[j]; fobuf[j] = to;
            }

    // ---- per-scale descriptors (uniform 256-px chunks) ----
    AllDesc ad;
    int block_base = 0;
    for (int s = 0; s < NUM_SCALES; ++s) {
        const int HW_dim = 128 >> s;             // 128,64,32,16
        const int HW     = HW_dim * HW_dim;
        const int C      = (int)(szs[s] / ((long)B * HW));
        const int pixels = B * HW;
        const int nblk   = pixels / PXB;

        ad.s[s].f          = fbuf[s];
        ad.s[s].fo         = fobuf[s];
        ad.s[s].C          = C;
        ad.s[s].W          = HW_dim;
        ad.s[s].HW         = HW;
        ad.s[s].block_base = block_base;
        ad.s[s].sub        = LAB_DIM / HW_dim;
        block_base += nblk;
    }

    msrd_kernel<<<block_base, THREADS>>>(ad, lab,
                                         scalar_ptrs[0], scalar_ptrs[1],
                                         (float*)d_out);
}